// round 9
// baseline (speedup 1.0000x reference)
#include <cuda_runtime.h>
#include <cstdint>

// ---------------- problem constants ----------------
#define MTOK 256
#define KDIM 1024
#define NDIM 2048
#define EXP  64
#define TOPK 8
#define CAP  32            // (MTOK*TOPK)/EXP, balanced routing
#define LTOT (MTOK*TOPK)   // 2048

// ---------------- tiling ----------------
#define NTHR 256
#define MT 128                          // flattened weight rows per tile
#define NCTA 148                        // one persistent CTA per SM
#define NTILE 1024                      // 64 experts x 16 n-tiles
#define CHUNK_K 32                      // k elems per stage chunk
#define STAGES 5
#define STAGE_BYTES (MT*CHUNK_K*4)      // 16384

// smem layout
#define OFF_LI 0                        // 32 ints (flat slot ids)
#define OFF_LW 128                      // 32 floats (routing weights)
#define OFF_STG 1024                    // 32 x 132 floats epilogue staging
#define SM_A   17920                    // token tiles in mma-fragment order
#define A_BYTES (CAP*KDIM*4)            // 131072
#define SM_B   (SM_A + A_BYTES)         // 148992
#define SMEM_TOTAL (SM_B + STAGES*STAGE_BYTES)   // 230912  (<= 232448 opt-in)

// ---------------- helpers ----------------
__device__ __forceinline__ uint32_t smem_u32(const void* p) {
    uint32_t a;
    asm("{ .reg .u64 t; cvta.to.shared.u64 t, %1; cvt.u32.u64 %0, t; }" : "=r"(a) : "l"(p));
    return a;
}

__device__ __forceinline__ void cpa16(uint32_t dst, const void* src) {
    asm volatile("cp.async.cg.shared.global [%0], [%1], 16;"
                 :: "r"(dst), "l"(src) : "memory");
}

#define MMA_TF32(d, a0, a1, a2, a3, b0, b1)                                   \
    asm volatile(                                                             \
        "mma.sync.aligned.m16n8k8.row.col.f32.tf32.tf32.f32 "                 \
        "{%0,%1,%2,%3}, {%4,%5,%6,%7}, {%8,%9}, {%0,%1,%2,%3};"               \
        : "+f"(d[0]), "+f"(d[1]), "+f"(d[2]), "+f"(d[3])                      \
        : "r"(a0), "r"(a1), "r"(a2), "r"(a3), "r"(b0), "r"(b1))

// issue one 16KB weight chunk (global chunk index gi) into given stage
__device__ __forceinline__ void issue_chunk(uint32_t sb, const float* __restrict__ B,
                                            int gi, int stage, int tid) {
    const uint32_t stage_base = sb + SM_B + stage * STAGE_BYTES;
    const float* src = B + (size_t)(gi >> 5) * (MT * KDIM) + (gi & 31) * CHUNK_K;
    #pragma unroll
    for (int q = 0; q < 4; ++q) {
        int id = tid + q * NTHR;
        int row = id >> 3, g = id & 7;
        cpa16(stage_base + row * 128 + ((g * 16) ^ ((row & 7) * 16)),
              src + (size_t)row * KDIM + g * 4);
    }
    asm volatile("cp.async.commit_group;" ::: "memory");
}

// warp-0 routing scan for expert e
__device__ __forceinline__ void route_expert(int e, int lane,
                                             const int* __restrict__ ids,
                                             const float* __restrict__ tw,
                                             int* li_s, float* lw_s) {
    int total = 0;
    #pragma unroll
    for (int base = 0; base < LTOT; base += 32) {
        int id = __ldg(ids + base + lane);
        unsigned m = __ballot_sync(0xffffffffu, id == e);
        if (id == e) {
            int slot = total + __popc(m & ((1u << lane) - 1u));
            li_s[slot] = base + lane;
            lw_s[slot] = __ldg(tw + base + lane);
        }
        total += __popc(m);
    }
}

// gather expert's 32 token rows into SM_A, tf32-rounded, mma B-fragment order
// element (t, k): kb16=k/16, f=t/8, j=(k%16)/4, slot=(4*(t%8)+k%4)^(kb16%8)
// byte = SM_A + ((kb16*4+f)*32 + slot)*16 + j*4
__device__ __forceinline__ void gather_A(char* smem, const float* __restrict__ A,
                                         const int* li_s, int tid) {
    const int kb16 = tid >> 2;           // k = tid*4
    const int j    = tid & 3;
    const int sw   = kb16 & 7;
    #pragma unroll 4
    for (int t = 0; t < CAP; ++t) {
        const int l = li_s[t];
        const float4 v = ((const float4*)(A + (size_t)(l >> 3) * KDIM))[tid];
        uint32_t r0, r1, r2, r3;
        asm("cvt.rna.tf32.f32 %0, %1;" : "=r"(r0) : "f"(v.x));
        asm("cvt.rna.tf32.f32 %0, %1;" : "=r"(r1) : "f"(v.y));
        asm("cvt.rna.tf32.f32 %0, %1;" : "=r"(r2) : "f"(v.z));
        asm("cvt.rna.tf32.f32 %0, %1;" : "=r"(r3) : "f"(v.w));
        const int f  = t >> 3;
        const int s4 = (t & 7) << 2;
        char* base = smem + SM_A + (((kb16 << 2) + f) << 9) + (j << 2);
        *(uint32_t*)(base + (((s4 + 0) ^ sw) << 4)) = r0;
        *(uint32_t*)(base + (((s4 + 1) ^ sw) << 4)) = r1;
        *(uint32_t*)(base + (((s4 + 2) ^ sw) << 4)) = r2;
        *(uint32_t*)(base + (((s4 + 3) ^ sw) << 4)) = r3;
    }
}

// ---------------- persistent fused grouped-GEMM kernel ----------------
__global__ void __launch_bounds__(NTHR, 1)
moe_gemm_kernel(const float* __restrict__ A,
                const float* __restrict__ B,
                const float* __restrict__ bias,
                const float* __restrict__ tw,
                const int*   __restrict__ ids,
                float* __restrict__ out) {
    extern __shared__ char smem[];
    const uint32_t sb = smem_u32(smem);
    const int tid  = threadIdx.x;
    const int w    = tid >> 5;
    const int lane = tid & 31;
    const int cta  = blockIdx.x;

    // tile range: CTAs 0..135 -> 7 tiles, 136..147 -> 6 tiles (covers 1024)
    const int t0     = (cta < 136) ? cta * 7 : 952 + (cta - 136) * 6;
    const int ntiles = (cta < 136) ? 7 : 6;
    const int TOT    = ntiles * 32;       // chunks this CTA
    const int c0     = t0 * 32;           // first global chunk
    int e = t0 >> 4;                      // current expert

    int*   li_s = (int*)(smem + OFF_LI);
    float* lw_s = (float*)(smem + OFF_LW);
    float* stg  = (float*)(smem + OFF_STG);   // 32 x 132 floats

    // ---- prologue: issue chunks c0..c0+3 into stages 0..3 ----
    #pragma unroll
    for (int c = 0; c < STAGES - 1; ++c)
        issue_chunk(sb, B, c0 + c, c, tid);

    // ---- routing + A gather for first expert (overlaps prologue loads) ----
    if (w == 0) route_expert(e, lane, ids, tw, li_s, lw_s);
    __syncthreads();
    gather_A(smem, A, li_s, tid);
    asm volatile("cp.async.wait_group 3;" ::: "memory");   // chunk c0 arrived

    // ---- main pipeline ----
    float acc[4][4] = {};
    const int rlo = (w << 4) + (lane >> 2);       // weight row in tile, 0..127
    const uint32_t swz = ((lane >> 2) & 7) << 4;  // (rlo&7)*16
    int cmp_s = 0;   // stage of chunk li
    int iss_s = STAGES - 1;   // stage for chunk li+4

    for (int li = 0; li < TOT; ++li) {
        __syncthreads();   // publishes awaited cp.async data; frees stage iss_s
        const int gi = c0 + li;

        // issue chunk li+4 into the stage consumed at iteration li-1
        if (li + 4 < TOT)
            issue_chunk(sb, B, gi + 4, iss_s, tid);

        // compute chunk gi from stage cmp_s
        {
            const int c32 = gi & 31;
            const char* stgp = smem + SM_B + cmp_s * STAGE_BYTES + rlo * 128;
            #pragma unroll
            for (int kb = 0; kb < 2; ++kb) {
                const int kb16 = c32 * 2 + kb;
                uint4 bq[4];
                #pragma unroll
                for (int f = 0; f < 4; ++f)
                    bq[f] = *(const uint4*)(smem + SM_A +
                            ((((kb16 << 2) + f) << 5) + (lane ^ (kb16 & 7))) * 16);
                #pragma unroll
                for (int d8 = 0; d8 < 2; ++d8) {
                    const int cb = (kb << 4) + (d8 << 3) + (lane & 3);
                    const uint32_t x0 = ((uint32_t)(cb << 2)) ^ swz;
                    const uint32_t x1 = ((uint32_t)((cb + 4) << 2)) ^ swz;
                    uint32_t a0 = *(const uint32_t*)(stgp + x0);
                    uint32_t a1 = *(const uint32_t*)(stgp + 1024 + x0);
                    uint32_t a2 = *(const uint32_t*)(stgp + x1);
                    uint32_t a3 = *(const uint32_t*)(stgp + 1024 + x1);
                    if (d8 == 0) {
                        MMA_TF32(acc[0], a0, a1, a2, a3, bq[0].x, bq[0].y);
                        MMA_TF32(acc[1], a0, a1, a2, a3, bq[1].x, bq[1].y);
                        MMA_TF32(acc[2], a0, a1, a2, a3, bq[2].x, bq[2].y);
                        MMA_TF32(acc[3], a0, a1, a2, a3, bq[3].x, bq[3].y);
                    } else {
                        MMA_TF32(acc[0], a0, a1, a2, a3, bq[0].z, bq[0].w);
                        MMA_TF32(acc[1], a0, a1, a2, a3, bq[1].z, bq[1].w);
                        MMA_TF32(acc[2], a0, a1, a2, a3, bq[2].z, bq[2].w);
                        MMA_TF32(acc[3], a0, a1, a2, a3, bq[3].z, bq[3].w);
                    }
                }
            }
        }

        // tile boundary: epilogue (prefetched B chunks stay in flight)
        if ((gi & 31) == 31) {
            const int tile = gi >> 5;
            const int r = tile * MT + rlo;        // flattened (e*N + n) row
            const float bv0 = bias[r];
            const float bv1 = bias[r + 8];
            #pragma unroll
            for (int f = 0; f < 4; ++f) {
                const int tk = (f << 3) + ((lane & 3) << 1);
                const float w0 = lw_s[tk], w1 = lw_s[tk + 1];
                stg[tk * 132 + rlo]           = (acc[f][0] + bv0) * w0;
                stg[(tk + 1) * 132 + rlo]     = (acc[f][1] + bv0) * w1;
                stg[tk * 132 + rlo + 8]       = (acc[f][2] + bv1) * w0;
                stg[(tk + 1) * 132 + rlo + 8] = (acc[f][3] + bv1) * w1;
            }
            __syncthreads();
            const int nbase = (tile & 15) * MT;
            #pragma unroll 4
            for (int idx = tid; idx < CAP * MT; idx += NTHR) {
                const int t = idx >> 7, n = idx & 127;
                out[(size_t)li_s[t] * NDIM + nbase + n] = stg[t * 132 + n];
            }
            #pragma unroll
            for (int f = 0; f < 4; ++f)
                #pragma unroll
                for (int cc = 0; cc < 4; ++cc)
                    acc[f][cc] = 0.0f;

            // expert boundary: rebuild routing + A tile (B stream unaffected)
            if (li + 1 < TOT && ((gi + 1) >> 9) != e) {
                e = (gi + 1) >> 9;
                __syncthreads();                       // scatter done reading li_s
                if (w == 0) route_expert(e, lane, ids, tw, li_s, lw_s);
                __syncthreads();
                gather_A(smem, A, li_s, tid);
                // next loop-top __syncthreads orders SM_A for compute
            }
        }

        // ensure chunk li+1 has arrived before next iteration's compute
        if (li + 4 < TOT)      asm volatile("cp.async.wait_group 3;" ::: "memory");
        else if (li + 3 < TOT) asm volatile("cp.async.wait_group 2;" ::: "memory");
        else if (li + 2 < TOT) asm volatile("cp.async.wait_group 1;" ::: "memory");
        else if (li + 1 < TOT) asm volatile("cp.async.wait_group 0;" ::: "memory");

        cmp_s = (cmp_s == STAGES - 1) ? 0 : cmp_s + 1;
        iss_s = (iss_s == STAGES - 1) ? 0 : iss_s + 1;
    }
}

// ---------------- host launch ----------------
extern "C" void kernel_launch(void* const* d_in, const int* in_sizes, int n_in,
                              void* d_out, int out_size) {
    const float* A    = (const float*)d_in[0];
    const float* B    = (const float*)d_in[1];
    const float* bias = (const float*)d_in[2];
    const float* tw   = (const float*)d_in[3];
    const int*   ids  = (const int*)d_in[4];
    float*       out  = (float*)d_out;

    static bool attr_set = false;
    if (!attr_set) {
        cudaFuncSetAttribute(moe_gemm_kernel,
                             cudaFuncAttributeMaxDynamicSharedMemorySize, SMEM_TOTAL);
        attr_set = true;
    }

    moe_gemm_kernel<<<NCTA, NTHR, SMEM_TOTAL>>>(A, B, bias, tw, ids, out);
}

// round 10
// speedup vs baseline: 1.1586x; 1.1586x over previous
#include <cuda_runtime.h>
#include <cstdint>

// ---------------- problem constants ----------------
#define MTOK 256
#define KDIM 1024
#define NDIM 2048
#define EXP  64
#define TOPK 8
#define CAP  32            // (MTOK*TOPK)/EXP, balanced routing
#define LTOT (MTOK*TOPK)   // 2048

// ---------------- tiling ----------------
#define NTHR 320                        // 8 consumer warps + 2 producer warps
#define NCONS 256                       // consumer threads
#define MT 128                          // flattened weight rows per tile
#define NCTA 148                        // one persistent CTA per SM
#define CHUNK_K 32                      // k elems per stage chunk
#define STAGES 6
#define DEPTH 5                         // cp.async groups in flight per producer
#define STAGE_BYTES (MT*CHUNK_K*4)      // 16384

// smem layout
#define OFF_FULL(s)  ((s)*16)           // full mbarriers (count=2)
#define OFF_EMPTY(s) ((s)*16 + 8)       // empty mbarriers (count=8)
#define OFF_LI 128                      // 32 ints (flat slot ids)
#define OFF_LW 256                      // 32 floats (routing weights)
#define SM_A   1024                     // token tiles in mma-fragment order
#define A_BYTES (CAP*KDIM*4)            // 131072
#define SM_B   (SM_A + A_BYTES)         // 132096
#define SMEM_TOTAL (SM_B + STAGES*STAGE_BYTES)   // 230400 (<= 232448 opt-in)

// ---------------- helpers ----------------
__device__ __forceinline__ uint32_t smem_u32(const void* p) {
    uint32_t a;
    asm("{ .reg .u64 t; cvta.to.shared.u64 t, %1; cvt.u32.u64 %0, t; }" : "=r"(a) : "l"(p));
    return a;
}

__device__ __forceinline__ void cpa16(uint32_t dst, const void* src) {
    asm volatile("cp.async.cg.shared.global [%0], [%1], 16;"
                 :: "r"(dst), "l"(src) : "memory");
}

__device__ __forceinline__ void mbar_wait(uint32_t addr, uint32_t parity) {
    asm volatile(
        "{\n\t.reg .pred P1;\n\t"
        "LAB_%=:\n\t"
        "mbarrier.try_wait.parity.acquire.cta.shared::cta.b64 P1, [%0], %1, 0x989680;\n\t"
        "@P1 bra.uni DONE_%=;\n\t"
        "bra.uni LAB_%=;\n\t"
        "DONE_%=:\n\t}"
        :: "r"(addr), "r"(parity) : "memory");
}

__device__ __forceinline__ void mbar_arrive(uint32_t addr) {
    asm volatile("mbarrier.arrive.shared.b64 _, [%0];" :: "r"(addr) : "memory");
}

#define MMA_TF32(d, a0, a1, a2, a3, b0, b1)                                   \
    asm volatile(                                                             \
        "mma.sync.aligned.m16n8k8.row.col.f32.tf32.tf32.f32 "                 \
        "{%0,%1,%2,%3}, {%4,%5,%6,%7}, {%8,%9}, {%0,%1,%2,%3};"               \
        : "+f"(d[0]), "+f"(d[1]), "+f"(d[2]), "+f"(d[3])                      \
        : "r"(a0), "r"(a1), "r"(a2), "r"(a3), "r"(b0), "r"(b1))

// warp-0 routing scan for expert e
__device__ __forceinline__ void route_expert(int e, int lane,
                                             const int* __restrict__ ids,
                                             const float* __restrict__ tw,
                                             int* li_s, float* lw_s) {
    int total = 0;
    #pragma unroll
    for (int base = 0; base < LTOT; base += 32) {
        int id = __ldg(ids + base + lane);
        unsigned m = __ballot_sync(0xffffffffu, id == e);
        if (id == e) {
            int slot = total + __popc(m & ((1u << lane) - 1u));
            li_s[slot] = base + lane;
            lw_s[slot] = __ldg(tw + base + lane);
        }
        total += __popc(m);
    }
}

// gather expert's 32 token rows into SM_A, tf32-rounded, mma B-fragment order
// element (t, k): kb16=k/16, f=t/8, j=(k%16)/4, slot=(4*(t%8)+k%4)^(kb16%8)
// byte = SM_A + ((kb16*4+f)*32 + slot)*16 + j*4      (uses consumer tids 0..255)
__device__ __forceinline__ void gather_A(char* smem, const float* __restrict__ A,
                                         const int* li_s, int tid) {
    const int kb16 = tid >> 2;           // k = tid*4
    const int j    = tid & 3;
    const int sw   = kb16 & 7;
    #pragma unroll 4
    for (int t = 0; t < CAP; ++t) {
        const int l = li_s[t];
        const float4 v = ((const float4*)(A + (size_t)(l >> 3) * KDIM))[tid];
        uint32_t r0, r1, r2, r3;
        asm("cvt.rna.tf32.f32 %0, %1;" : "=r"(r0) : "f"(v.x));
        asm("cvt.rna.tf32.f32 %0, %1;" : "=r"(r1) : "f"(v.y));
        asm("cvt.rna.tf32.f32 %0, %1;" : "=r"(r2) : "f"(v.z));
        asm("cvt.rna.tf32.f32 %0, %1;" : "=r"(r3) : "f"(v.w));
        const int f  = t >> 3;
        const int s4 = (t & 7) << 2;
        char* base = smem + SM_A + (((kb16 << 2) + f) << 9) + (j << 2);
        *(uint32_t*)(base + (((s4 + 0) ^ sw) << 4)) = r0;
        *(uint32_t*)(base + (((s4 + 1) ^ sw) << 4)) = r1;
        *(uint32_t*)(base + (((s4 + 2) ^ sw) << 4)) = r2;
        *(uint32_t*)(base + (((s4 + 3) ^ sw) << 4)) = r3;
    }
}

// ---------------- persistent warp-specialized grouped-GEMM kernel ----------------
__global__ void __launch_bounds__(NTHR, 1)
moe_gemm_kernel(const float* __restrict__ A,
                const float* __restrict__ B,
                const float* __restrict__ bias,
                const float* __restrict__ tw,
                const int*   __restrict__ ids,
                float* __restrict__ out) {
    extern __shared__ char smem[];
    const uint32_t sb = smem_u32(smem);
    const int tid  = threadIdx.x;
    const int w    = tid >> 5;
    const int lane = tid & 31;
    const int cta  = blockIdx.x;

    // tile range: CTAs 0..135 -> 7 tiles, 136..147 -> 6 tiles (covers 1024)
    const int t0     = (cta < 136) ? cta * 7 : 952 + (cta - 136) * 6;
    const int ntiles = (cta < 136) ? 7 : 6;
    const int TOT    = ntiles * 32;       // chunks this CTA
    const int c0     = t0 * 32;           // first global chunk

    int*   li_s = (int*)(smem + OFF_LI);
    float* lw_s = (float*)(smem + OFF_LW);

    if (tid == 0) {
        #pragma unroll
        for (int s = 0; s < STAGES; ++s) {
            asm volatile("mbarrier.init.shared.b64 [%0], 2;" :: "r"(sb + OFF_FULL(s))  : "memory");
            asm volatile("mbarrier.init.shared.b64 [%0], 8;" :: "r"(sb + OFF_EMPTY(s)) : "memory");
        }
    }
    __syncthreads();   // only CTA-wide barrier in the kernel

    if (w >= 8) {
        // ================= producer warps (w = 8, 9) =================
        const int pid = w - 8;               // half: rows pid*64 .. pid*64+63
        int s = 0, k = 0;                    // issue cursor + phase
        int as_ = 0;                         // arrive cursor
        int pending = 0;
        for (int c = 0; c < TOT; ++c) {
            mbar_wait(sb + OFF_EMPTY(s), 1u ^ (uint32_t)k);
            const int gc = c0 + c;
            const float* src = B + (size_t)(gc >> 5) * (MT * KDIM) + (gc & 31) * CHUNK_K;
            const uint32_t st_base = sb + SM_B + s * STAGE_BYTES;
            #pragma unroll
            for (int q = 0; q < 16; ++q) {
                const int id  = q * 32 + lane;
                const int row = pid * 64 + (id >> 3);
                const int g   = id & 7;
                cpa16(st_base + row * 128 + ((g * 16) ^ ((row & 7) * 16)),
                      src + (size_t)row * KDIM + g * 4);
            }
            asm volatile("cp.async.commit_group;" ::: "memory");
            if (++pending == DEPTH) {
                asm volatile("cp.async.wait_group %0;" :: "n"(DEPTH - 1) : "memory");
                if (lane == 0) mbar_arrive(sb + (uint32_t)as_ * 16);   // full[as_]
                --pending;
                if (++as_ == STAGES) as_ = 0;
            }
            if (++s == STAGES) { s = 0; k ^= 1; }
        }
        // drain: pending == DEPTH-1 == 4 (TOT >= DEPTH always)
        asm volatile("cp.async.wait_group 3;" ::: "memory");
        if (lane == 0) mbar_arrive(sb + (uint32_t)as_ * 16);
        if (++as_ == STAGES) as_ = 0;
        asm volatile("cp.async.wait_group 2;" ::: "memory");
        if (lane == 0) mbar_arrive(sb + (uint32_t)as_ * 16);
        if (++as_ == STAGES) as_ = 0;
        asm volatile("cp.async.wait_group 1;" ::: "memory");
        if (lane == 0) mbar_arrive(sb + (uint32_t)as_ * 16);
        if (++as_ == STAGES) as_ = 0;
        asm volatile("cp.async.wait_group 0;" ::: "memory");
        if (lane == 0) mbar_arrive(sb + (uint32_t)as_ * 16);
        return;
    }

    // ================= consumer warps (w = 0..7) =================
    int e = t0 >> 4;                      // current expert
    if (w == 0) route_expert(e, lane, ids, tw, li_s, lw_s);
    asm volatile("bar.sync 1, %0;" :: "n"(NCONS) : "memory");
    gather_A(smem, A, li_s, tid);
    asm volatile("bar.sync 1, %0;" :: "n"(NCONS) : "memory");

    float acc[4][4] = {};
    const int rlo = (w << 4) + (lane >> 2);       // weight row in tile, 0..127
    const uint32_t swz = ((lane >> 2) & 7) << 4;  // (rlo&7)*16
    int s = 0, k = 0;

    for (int li = 0; li < TOT; ++li) {
        mbar_wait(sb + OFF_FULL(s), (uint32_t)k);

        // compute chunk li from stage s
        {
            const int c32 = li & 31;
            const char* stgp = smem + SM_B + s * STAGE_BYTES + rlo * 128;
            #pragma unroll
            for (int kb = 0; kb < 2; ++kb) {
                const int kb16 = c32 * 2 + kb;
                uint4 bq[4];
                #pragma unroll
                for (int f = 0; f < 4; ++f)
                    bq[f] = *(const uint4*)(smem + SM_A +
                            ((((kb16 << 2) + f) << 5) + (lane ^ (kb16 & 7))) * 16);
                #pragma unroll
                for (int d8 = 0; d8 < 2; ++d8) {
                    const int cb = (kb << 4) + (d8 << 3) + (lane & 3);
                    const uint32_t x0 = ((uint32_t)(cb << 2)) ^ swz;
                    const uint32_t x1 = ((uint32_t)((cb + 4) << 2)) ^ swz;
                    uint32_t a0 = *(const uint32_t*)(stgp + x0);
                    uint32_t a1 = *(const uint32_t*)(stgp + 1024 + x0);
                    uint32_t a2 = *(const uint32_t*)(stgp + x1);
                    uint32_t a3 = *(const uint32_t*)(stgp + 1024 + x1);
                    if (d8 == 0) {
                        MMA_TF32(acc[0], a0, a1, a2, a3, bq[0].x, bq[0].y);
                        MMA_TF32(acc[1], a0, a1, a2, a3, bq[1].x, bq[1].y);
                        MMA_TF32(acc[2], a0, a1, a2, a3, bq[2].x, bq[2].y);
                        MMA_TF32(acc[3], a0, a1, a2, a3, bq[3].x, bq[3].y);
                    } else {
                        MMA_TF32(acc[0], a0, a1, a2, a3, bq[0].z, bq[0].w);
                        MMA_TF32(acc[1], a0, a1, a2, a3, bq[1].z, bq[1].w);
                        MMA_TF32(acc[2], a0, a1, a2, a3, bq[2].z, bq[2].w);
                        MMA_TF32(acc[3], a0, a1, a2, a3, bq[3].z, bq[3].w);
                    }
                }
            }
        }
        if (lane == 0) mbar_arrive(sb + OFF_EMPTY(s));   // free stage ASAP

        // tile boundary: per-warp direct epilogue (32B-sector aligned stores)
        if ((li & 31) == 31) {
            const int tile  = (c0 + li) >> 5;
            const int r     = tile * MT + rlo;       // flattened (e*N + n) row
            const int nbase = (tile & 15) * MT;
            const float bv0 = __ldg(bias + r);
            const float bv1 = __ldg(bias + r + 8);
            #pragma unroll
            for (int f = 0; f < 4; ++f) {
                const int tk = (f << 3) + ((lane & 3) << 1);
                const float w0 = lw_s[tk], w1 = lw_s[tk + 1];
                float* o0 = out + (size_t)li_s[tk]     * NDIM + nbase + rlo;
                float* o1 = out + (size_t)li_s[tk + 1] * NDIM + nbase + rlo;
                o0[0] = (acc[f][0] + bv0) * w0;
                o1[0] = (acc[f][1] + bv0) * w1;
                o0[8] = (acc[f][2] + bv1) * w0;
                o1[8] = (acc[f][3] + bv1) * w1;
            }
            #pragma unroll
            for (int f = 0; f < 4; ++f)
                #pragma unroll
                for (int cc = 0; cc < 4; ++cc)
                    acc[f][cc] = 0.0f;

            // expert boundary: rebuild routing + A tile (B stream keeps running)
            const int gnext = c0 + li + 1;
            if (li + 1 < TOT && (gnext >> 9) != e) {
                e = gnext >> 9;
                asm volatile("bar.sync 1, %0;" :: "n"(NCONS) : "memory"); // all done with li_s / SM_A
                if (w == 0) route_expert(e, lane, ids, tw, li_s, lw_s);
                asm volatile("bar.sync 1, %0;" :: "n"(NCONS) : "memory");
                gather_A(smem, A, li_s, tid);
                asm volatile("bar.sync 1, %0;" :: "n"(NCONS) : "memory");
            }
        }

        if (++s == STAGES) { s = 0; k ^= 1; }
    }
}

// ---------------- host launch ----------------
extern "C" void kernel_launch(void* const* d_in, const int* in_sizes, int n_in,
                              void* d_out, int out_size) {
    const float* A    = (const float*)d_in[0];
    const float* B    = (const float*)d_in[1];
    const float* bias = (const float*)d_in[2];
    const float* tw   = (const float*)d_in[3];
    const int*   ids  = (const int*)d_in[4];
    float*       out  = (float*)d_out;

    static bool attr_set = false;
    if (!attr_set) {
        cudaFuncSetAttribute(moe_gemm_kernel,
                             cudaFuncAttributeMaxDynamicSharedMemorySize, SMEM_TOTAL);
        attr_set = true;
    }

    moe_gemm_kernel<<<NCTA, NTHR, SMEM_TOTAL>>>(A, B, bias, tw, ids, out);
}

// round 12
// speedup vs baseline: 1.2397x; 1.0700x over previous
#include <cuda_runtime.h>
#include <cstdint>

// ---------------- problem constants ----------------
#define MTOK 256
#define KDIM 1024
#define NDIM 2048
#define EXP  64
#define TOPK 8
#define CAP  32            // (MTOK*TOPK)/EXP, balanced routing
#define LTOT (MTOK*TOPK)   // 2048

// ---------------- tiling ----------------
#define NTHR 384                        // 8 consumer warps + 4 producer warps
#define NCONS 256                       // consumer threads
#define MT 128                          // weight rows per tile
#define NCTA 128                        // 2 CTAs per expert
#define TG 4                            // tiles per group (K-outer within group)
#define NGROUP 2                        // groups per CTA (8 tiles total)
#define CHUNK_K 32                      // k elems per stage chunk
#define NKC (KDIM/CHUNK_K)              // 32 k-chunks
#define STAGES 6
#define DEPTH 4                         // cp.async groups in flight per producer
#define STAGE_BYTES (MT*CHUNK_K*4)      // 16384

// smem layout
#define OFF_FULL(s)  ((s)*16)           // full mbarriers (count=4)
#define OFF_EMPTY(s) ((s)*16 + 8)       // empty mbarriers (count=8)
#define OFF_LI 128                      // 32 ints (flat slot ids)
#define OFF_LW 256                      // 32 floats (routing weights)
#define SM_A   1024                     // token tiles in mma-fragment order
#define A_BYTES (CAP*KDIM*4)            // 131072
#define SM_B   (SM_A + A_BYTES)         // 132096
#define SMEM_TOTAL (SM_B + STAGES*STAGE_BYTES)   // 230400 (<= 232448 opt-in)

// ---------------- helpers ----------------
__device__ __forceinline__ uint32_t smem_u32(const void* p) {
    uint32_t a;
    asm("{ .reg .u64 t; cvta.to.shared.u64 t, %1; cvt.u32.u64 %0, t; }" : "=r"(a) : "l"(p));
    return a;
}

__device__ __forceinline__ void cpa16(uint32_t dst, const void* src) {
    asm volatile("cp.async.cg.shared.global [%0], [%1], 16;"
                 :: "r"(dst), "l"(src) : "memory");
}

__device__ __forceinline__ void mbar_wait(uint32_t addr, uint32_t parity) {
    asm volatile(
        "{\n\t.reg .pred P1;\n\t"
        "LAB_%=:\n\t"
        "mbarrier.try_wait.parity.acquire.cta.shared::cta.b64 P1, [%0], %1, 0x989680;\n\t"
        "@P1 bra.uni DONE_%=;\n\t"
        "bra.uni LAB_%=;\n\t"
        "DONE_%=:\n\t}"
        :: "r"(addr), "r"(parity) : "memory");
}

__device__ __forceinline__ void mbar_arrive(uint32_t addr) {
    asm volatile("mbarrier.arrive.shared.b64 _, [%0];" :: "r"(addr) : "memory");
}

#define MMA_TF32(d, a0, a1, a2, a3, b0, b1)                                   \
    asm volatile(                                                             \
        "mma.sync.aligned.m16n8k8.row.col.f32.tf32.tf32.f32 "                 \
        "{%0,%1,%2,%3}, {%4,%5,%6,%7}, {%8,%9}, {%0,%1,%2,%3};"               \
        : "+f"(d[0]), "+f"(d[1]), "+f"(d[2]), "+f"(d[3])                      \
        : "r"(a0), "r"(a1), "r"(a2), "r"(a3), "r"(b0), "r"(b1))

// warp-0 routing scan for expert e
__device__ __forceinline__ void route_expert(int e, int lane,
                                             const int* __restrict__ ids,
                                             const float* __restrict__ tw,
                                             int* li_s, float* lw_s) {
    int total = 0;
    #pragma unroll
    for (int base = 0; base < LTOT; base += 32) {
        int id = __ldg(ids + base + lane);
        unsigned m = __ballot_sync(0xffffffffu, id == e);
        if (id == e) {
            int slot = total + __popc(m & ((1u << lane) - 1u));
            li_s[slot] = base + lane;
            lw_s[slot] = __ldg(tw + base + lane);
        }
        total += __popc(m);
    }
}

// gather expert's 32 token rows into SM_A, tf32-rounded, mma B-fragment order
// element (t, k): kb16=k/16, f=t/8, j=(k%16)/4, slot=(4*(t%8)+k%4)^(kb16%8)
// byte = SM_A + ((kb16*4+f)*32 + slot)*16 + j*4      (uses consumer tids 0..255)
__device__ __forceinline__ void gather_A(char* smem, const float* __restrict__ A,
                                         const int* li_s, int tid) {
    const int kb16 = tid >> 2;           // k = tid*4
    const int j    = tid & 3;
    const int sw   = kb16 & 7;
    #pragma unroll 4
    for (int t = 0; t < CAP; ++t) {
        const int l = li_s[t];
        const float4 v = ((const float4*)(A + (size_t)(l >> 3) * KDIM))[tid];
        uint32_t r0, r1, r2, r3;
        asm("cvt.rna.tf32.f32 %0, %1;" : "=r"(r0) : "f"(v.x));
        asm("cvt.rna.tf32.f32 %0, %1;" : "=r"(r1) : "f"(v.y));
        asm("cvt.rna.tf32.f32 %0, %1;" : "=r"(r2) : "f"(v.z));
        asm("cvt.rna.tf32.f32 %0, %1;" : "=r"(r3) : "f"(v.w));
        const int f  = t >> 3;
        const int s4 = (t & 7) << 2;
        char* base = smem + SM_A + (((kb16 << 2) + f) << 9) + (j << 2);
        *(uint32_t*)(base + (((s4 + 0) ^ sw) << 4)) = r0;
        *(uint32_t*)(base + (((s4 + 1) ^ sw) << 4)) = r1;
        *(uint32_t*)(base + (((s4 + 2) ^ sw) << 4)) = r2;
        *(uint32_t*)(base + (((s4 + 3) ^ sw) << 4)) = r3;
    }
}

// ---------------- persistent warp-specialized grouped-GEMM kernel ----------------
__global__ void __launch_bounds__(NTHR, 1)
moe_gemm_kernel(const float* __restrict__ A,
                const float* __restrict__ B,
                const float* __restrict__ bias,
                const float* __restrict__ tw,
                const int*   __restrict__ ids,
                float* __restrict__ out) {
    extern __shared__ char smem[];
    const uint32_t sb = smem_u32(smem);
    const int tid  = threadIdx.x;
    const int w    = tid >> 5;
    const int lane = tid & 31;
    const int cta  = blockIdx.x;
    const int e    = cta >> 1;            // expert (fixed per CTA)
    const int half = cta & 1;
    const int t0   = e * 16 + half * 8;   // first flattened tile

    int*   li_s = (int*)(smem + OFF_LI);
    float* lw_s = (float*)(smem + OFF_LW);

    if (tid == 0) {
        #pragma unroll
        for (int s = 0; s < STAGES; ++s) {
            asm volatile("mbarrier.init.shared.b64 [%0], 4;" :: "r"(sb + OFF_FULL(s))  : "memory");
            asm volatile("mbarrier.init.shared.b64 [%0], 8;" :: "r"(sb + OFF_EMPTY(s)) : "memory");
        }
    }
    __syncthreads();   // only CTA-wide barrier in the kernel

    if (w >= 8) {
        // ============ producer warps (w = 8..11): quarter-chunks of 4KB ============
        const int pid = w - 8;               // rows pid*32 .. pid*32+31
        int s = 0, k = 0;                    // issue cursor + phase
        int as_ = 0;                         // full-arrive cursor
        int pending = 0;
        for (int g = 0; g < NGROUP; ++g)
        for (int kc = 0; kc < NKC; ++kc)
        #pragma unroll
        for (int t = 0; t < TG; ++t) {
            mbar_wait(sb + OFF_EMPTY(s), 1u ^ (uint32_t)k);
            const float* src = B + (size_t)(t0 + g * TG + t) * (MT * KDIM) + kc * CHUNK_K;
            const uint32_t st_base = sb + SM_B + s * STAGE_BYTES;
            #pragma unroll
            for (int q = 0; q < 8; ++q) {
                const int id  = q * 32 + lane;
                const int row = pid * 32 + (id >> 3);
                const int gg  = id & 7;
                cpa16(st_base + row * 128 + ((gg * 16) ^ ((row & 7) * 16)),
                      src + (size_t)row * KDIM + gg * 4);
            }
            asm volatile("cp.async.commit_group;" ::: "memory");
            if (++pending == DEPTH) {
                asm volatile("cp.async.wait_group %0;" :: "n"(DEPTH - 1) : "memory");
                if (lane == 0) mbar_arrive(sb + (uint32_t)as_ * 16);   // full[as_]
                --pending;
                if (++as_ == STAGES) as_ = 0;
            }
            if (++s == STAGES) { s = 0; k ^= 1; }
        }
        // drain: pending == DEPTH-1 == 3
        asm volatile("cp.async.wait_group 2;" ::: "memory");
        if (lane == 0) mbar_arrive(sb + (uint32_t)as_ * 16);
        if (++as_ == STAGES) as_ = 0;
        asm volatile("cp.async.wait_group 1;" ::: "memory");
        if (lane == 0) mbar_arrive(sb + (uint32_t)as_ * 16);
        if (++as_ == STAGES) as_ = 0;
        asm volatile("cp.async.wait_group 0;" ::: "memory");
        if (lane == 0) mbar_arrive(sb + (uint32_t)as_ * 16);
        return;
    }

    // ============ consumer warps (w = 0..7) ============
    if (w == 0) route_expert(e, lane, ids, tw, li_s, lw_s);
    asm volatile("bar.sync 1, %0;" :: "n"(NCONS) : "memory");
    gather_A(smem, A, li_s, tid);
    asm volatile("bar.sync 1, %0;" :: "n"(NCONS) : "memory");

    float acc[TG][4][4] = {};                     // [tile][token-frag][c]
    const int rlo = (w << 4) + (lane >> 2);       // weight row in tile, 0..127
    const uint32_t swz = ((lane >> 2) & 7) << 4;  // (rlo&7)*16
    int s = 0, k = 0;

    for (int g = 0; g < NGROUP; ++g) {
        for (int kc = 0; kc < NKC; ++kc) {
            // token fragments for this k-chunk: loaded ONCE, reused for TG tiles.
            // Issued before the full-wait so LDS latency hides under it.
            uint4 bq[2][4];
            #pragma unroll
            for (int h = 0; h < 2; ++h) {
                const int kb16 = kc * 2 + h;
                #pragma unroll
                for (int f = 0; f < 4; ++f)
                    bq[h][f] = *(const uint4*)(smem + SM_A +
                            ((((kb16 << 2) + f) << 5) + (lane ^ (kb16 & 7))) * 16);
            }
            #pragma unroll
            for (int t = 0; t < TG; ++t) {
                mbar_wait(sb + OFF_FULL(s), (uint32_t)k);
                const char* stgp = smem + SM_B + s * STAGE_BYTES + rlo * 128;
                #pragma unroll
                for (int h = 0; h < 2; ++h) {
                    #pragma unroll
                    for (int d8 = 0; d8 < 2; ++d8) {
                        const int cb = (h << 4) + (d8 << 3) + (lane & 3);
                        const uint32_t x0 = ((uint32_t)(cb << 2)) ^ swz;
                        const uint32_t x1 = ((uint32_t)((cb + 4) << 2)) ^ swz;
                        uint32_t a0 = *(const uint32_t*)(stgp + x0);
                        uint32_t a1 = *(const uint32_t*)(stgp + 1024 + x0);
                        uint32_t a2 = *(const uint32_t*)(stgp + x1);
                        uint32_t a3 = *(const uint32_t*)(stgp + 1024 + x1);
                        if (d8 == 0) {
                            MMA_TF32(acc[t][0], a0, a1, a2, a3, bq[h][0].x, bq[h][0].y);
                            MMA_TF32(acc[t][1], a0, a1, a2, a3, bq[h][1].x, bq[h][1].y);
                            MMA_TF32(acc[t][2], a0, a1, a2, a3, bq[h][2].x, bq[h][2].y);
                            MMA_TF32(acc[t][3], a0, a1, a2, a3, bq[h][3].x, bq[h][3].y);
                        } else {
                            MMA_TF32(acc[t][0], a0, a1, a2, a3, bq[h][0].z, bq[h][0].w);
                            MMA_TF32(acc[t][1], a0, a1, a2, a3, bq[h][1].z, bq[h][1].w);
                            MMA_TF32(acc[t][2], a0, a1, a2, a3, bq[h][2].z, bq[h][2].w);
                            MMA_TF32(acc[t][3], a0, a1, a2, a3, bq[h][3].z, bq[h][3].w);
                        }
                    }
                }
                if (lane == 0) mbar_arrive(sb + OFF_EMPTY(s));   // free stage ASAP
                if (++s == STAGES) { s = 0; k ^= 1; }
            }
        }

        // group epilogue: 4 tiles done; producers keep streaming next group
        #pragma unroll
        for (int t = 0; t < TG; ++t) {
            const int tile  = t0 + g * TG + t;
            const int r     = tile * MT + rlo;       // flattened (e*N + n) row
            const int nbase = (tile & 15) * MT;
            const float bv0 = __ldg(bias + r);
            const float bv1 = __ldg(bias + r + 8);
            #pragma unroll
            for (int f = 0; f < 4; ++f) {
                const int tk = (f << 3) + ((lane & 3) << 1);
                const float w0 = lw_s[tk], w1 = lw_s[tk + 1];
                float* o0 = out + (size_t)li_s[tk]     * NDIM + nbase + rlo;
                float* o1 = out + (size_t)li_s[tk + 1] * NDIM + nbase + rlo;
                o0[0] = (acc[t][f][0] + bv0) * w0;
                o1[0] = (acc[t][f][1] + bv0) * w1;
                o0[8] = (acc[t][f][2] + bv1) * w0;
                o1[8] = (acc[t][f][3] + bv1) * w1;
            }
            #pragma unroll
            for (int f = 0; f < 4; ++f)
                #pragma unroll
                for (int cc = 0; cc < 4; ++cc)
                    acc[t][f][cc] = 0.0f;
        }
    }
}

// ---------------- host launch ----------------
extern "C" void kernel_launch(void* const* d_in, const int* in_sizes, int n_in,
                              void* d_out, int out_size) {
    const float* A    = (const float*)d_in[0];
    const float* B    = (const float*)d_in[1];
    const float* bias = (const float*)d_in[2];
    const float* tw   = (const float*)d_in[3];
    const int*   ids  = (const int*)d_in[4];
    float*       out  = (float*)d_out;

    static bool attr_set = false;
    if (!attr_set) {
        cudaFuncSetAttribute(moe_gemm_kernel,
                             cudaFuncAttributeMaxDynamicSharedMemorySize, SMEM_TOTAL);
        attr_set = true;
    }

    moe_gemm_kernel<<<NCTA, NTHR, SMEM_TOTAL>>>(A, B, bias, tw, ids, out);
}